// round 2
// baseline (speedup 1.0000x reference)
#include <cuda_runtime.h>
#include <cuda_bf16.h>
#include <math.h>

// Scratch: per-frame max log-softmax scores. B*T = 262144 for this problem;
// sized 1<<19 for headroom. (__device__ global, not an allocation.)
__device__ float g_maxscore[1 << 19];

// ---------------------------------------------------------------------------
// Pass 1: one warp per (b,t) row of V=128 logits (grid-stride over rows).
// Computes argmax (token) and max log-softmax = -log(sum exp(x - max)).
// Writes token as float into out[0 : B*T], score into g_maxscore.
// ---------------------------------------------------------------------------
__global__ void ctc_pass1_v128(const float* __restrict__ feat,
                               float* __restrict__ tok_out,
                               int rows) {
    int lane = threadIdx.x & 31;
    int warp0 = (blockIdx.x * blockDim.x + threadIdx.x) >> 5;
    int nwarps = (gridDim.x * blockDim.x) >> 5;

    for (int row = warp0; row < rows; row += nwarps) {
        const float4* p = reinterpret_cast<const float4*>(feat) + (size_t)row * 32;
        float4 v = p[lane];

        // local max + index (first-index tie break)
        float m = v.x; int mi = 0;
        if (v.y > m) { m = v.y; mi = 1; }
        if (v.z > m) { m = v.z; mi = 2; }
        if (v.w > m) { m = v.w; mi = 3; }
        mi += lane * 4;

        #pragma unroll
        for (int o = 16; o; o >>= 1) {
            float om = __shfl_xor_sync(0xFFFFFFFFu, m, o);
            int   oi = __shfl_xor_sync(0xFFFFFFFFu, mi, o);
            if (om > m || (om == m && oi < mi)) { m = om; mi = oi; }
        }

        float s = __expf(v.x - m) + __expf(v.y - m) + __expf(v.z - m) + __expf(v.w - m);
        #pragma unroll
        for (int o = 16; o; o >>= 1) s += __shfl_xor_sync(0xFFFFFFFFu, s, o);

        if (lane == 0) {
            tok_out[row] = (float)mi;       // token, exact small int in fp32
            g_maxscore[row] = -__logf(s);   // max(log_softmax) = m - lse = -log(s)
        }
    }
}

// Generic fallback for V != 128 (strided warp loop). Not expected to run.
__global__ void ctc_pass1_gen(const float* __restrict__ feat,
                              float* __restrict__ tok_out,
                              int rows, int V) {
    int warp = (blockIdx.x * blockDim.x + threadIdx.x) >> 5;
    int lane = threadIdx.x & 31;
    if (warp >= rows) return;
    const float* row = feat + (size_t)warp * V;

    float m = -INFINITY; int mi = 0;
    for (int i = lane; i < V; i += 32) {
        float x = row[i];
        if (x > m) { m = x; mi = i; }
    }
    #pragma unroll
    for (int o = 16; o; o >>= 1) {
        float om = __shfl_xor_sync(0xFFFFFFFFu, m, o);
        int   oi = __shfl_xor_sync(0xFFFFFFFFu, mi, o);
        if (om > m || (om == m && oi < mi)) { m = om; mi = oi; }
    }
    float s = 0.f;
    for (int i = lane; i < V; i += 32) s += __expf(row[i] - m);
    #pragma unroll
    for (int o = 16; o; o >>= 1) s += __shfl_xor_sync(0xFFFFFFFFu, s, o);
    if (lane == 0) { tok_out[warp] = (float)mi; g_maxscore[warp] = -__logf(s); }
}

// ---------------------------------------------------------------------------
// Pass 2: CTC collapse mask + masked sum of frame scores. One block per batch.
// keep = (tok != 0) && (tok != prev) && (t < len)
// ---------------------------------------------------------------------------
__global__ void ctc_pass2(const float* __restrict__ tok,
                          const int* __restrict__ lengths,
                          float* __restrict__ keep_out,
                          float* __restrict__ score_out,
                          int T) {
    int b = blockIdx.x;
    int len = lengths[b];
    const float* trow = tok + (size_t)b * T;
    float* krow = keep_out + (size_t)b * T;
    const float* srow = g_maxscore + (size_t)b * T;

    float acc = 0.f;
    for (int t = threadIdx.x; t < T; t += blockDim.x) {
        int cur  = (int)trow[t];
        int prev = (t == 0) ? 0 : (int)trow[t - 1];
        bool valid = (t < len);
        krow[t] = (cur != 0 && cur != prev && valid) ? 1.0f : 0.0f;
        if (valid) acc += srow[t];
    }

    __shared__ float sh[256];
    sh[threadIdx.x] = acc;
    __syncthreads();
    #pragma unroll
    for (int o = 128; o; o >>= 1) {
        if (threadIdx.x < o) sh[threadIdx.x] += sh[threadIdx.x + o];
        __syncthreads();
    }
    if (threadIdx.x == 0) score_out[b] = sh[0];
}

extern "C" void kernel_launch(void* const* d_in, const int* in_sizes, int n_in,
                              void* d_out, int out_size) {
    const float* feat    = (const float*)d_in[0];
    const int*   lengths = (const int*)d_in[1];

    int B = in_sizes[1];
    int T = (out_size - B) / (2 * B);          // out = tokens(B*T) + keep(B*T) + scores(B)
    int V = (int)((long long)in_sizes[0] / ((long long)B * T));
    int rows = B * T;

    float* out   = (float*)d_out;
    float* tok   = out;
    float* keep  = out + (size_t)rows;
    float* score = out + 2 * (size_t)rows;

    const int threads = 512;                   // 16 warps/block
    if (V == 128) {
        // Grid-stride: 2 waves' worth of CTAs on 148 SMs covers rows with
        // low tail sensitivity; rows=262144 -> each warp handles ~18 rows.
        int blocks = 148 * 6;
        int maxBlocks = (rows + 15) / 16;
        if (blocks > maxBlocks) blocks = maxBlocks;
        ctc_pass1_v128<<<blocks, threads>>>(feat, tok, rows);
    } else {
        int blocks = (rows + 15) / 16;
        ctc_pass1_gen<<<blocks, threads>>>(feat, tok, rows, V);
    }
    ctc_pass2<<<B, 256>>>(tok, lengths, keep, score, T);
}

// round 3
// speedup vs baseline: 1.7863x; 1.7863x over previous
#include <cuda_runtime.h>
#include <cuda_bf16.h>
#include <math.h>

// Scratch: per-frame max log-softmax scores (B*T = 262144 here; headroom).
__device__ float g_maxscore[1 << 19];

__device__ __forceinline__ unsigned f2ord(float x) {
    unsigned b = __float_as_uint(x);
    return (b & 0x80000000u) ? ~b : (b | 0x80000000u);
}
__device__ __forceinline__ float ord2f(unsigned u) {
    return __uint_as_float((u & 0x80000000u) ? (u ^ 0x80000000u) : ~u);
}

// ---------------------------------------------------------------------------
// Pass 1 (V=128): one warp per 4 consecutive rows -> 4 independent LDG.128 +
// 4 interleaved reduction chains. REDUX for max/argmax, 5xSHFL for sum-exp.
// rows must be a multiple of 4 (host guarantees; else generic kernel runs).
// ---------------------------------------------------------------------------
__global__ void ctc_pass1_v128x4(const float* __restrict__ feat,
                                 float* __restrict__ tok_out,
                                 int rows) {
    const int lane   = threadIdx.x & 31;
    const int warpId = (blockIdx.x * blockDim.x + threadIdx.x) >> 5;
    const int nwarps = (gridDim.x * blockDim.x) >> 5;
    const float4* f4 = reinterpret_cast<const float4*>(feat);

    for (int row0 = warpId * 4; row0 < rows; row0 += nwarps * 4) {
        float4 v[4];
        #pragma unroll
        for (int r = 0; r < 4; r++)
            v[r] = f4[(size_t)(row0 + r) * 32 + lane];

        float tokv[4], scorev[4];
        #pragma unroll
        for (int r = 0; r < 4; r++) {
            // lane-local max + first index among 4
            float m = v[r].x; int mi = 0;
            if (v[r].y > m) { m = v[r].y; mi = 1; }
            if (v[r].z > m) { m = v[r].z; mi = 2; }
            if (v[r].w > m) { m = v[r].w; mi = 3; }
            mi += lane * 4;

            // warp max via REDUX on order-preserving uint
            unsigned mu = f2ord(m);
            unsigned Mu = __reduce_max_sync(0xFFFFFFFFu, mu);
            float M = ord2f(Mu);

            // first-occurrence argmax: min index among lanes hitting M
            unsigned cand = (mu == Mu) ? (unsigned)mi : 0xFFFFFFFFu;
            unsigned amin = __reduce_min_sync(0xFFFFFFFFu, cand);

            // sum exp(x - M)
            float s = __expf(v[r].x - M) + __expf(v[r].y - M) +
                      __expf(v[r].z - M) + __expf(v[r].w - M);
            #pragma unroll
            for (int o = 16; o; o >>= 1)
                s += __shfl_xor_sync(0xFFFFFFFFu, s, o);

            tokv[r]   = (float)amin;
            scorev[r] = -__logf(s);   // max(log_softmax) = -log(sum exp(x-M))
        }

        if (lane == 0) {
            *reinterpret_cast<float4*>(tok_out + row0) =
                make_float4(tokv[0], tokv[1], tokv[2], tokv[3]);
            *reinterpret_cast<float4*>(g_maxscore + row0) =
                make_float4(scorev[0], scorev[1], scorev[2], scorev[3]);
        }
    }
}

// Generic fallback (any V, any rows). Not expected to run for this shape.
__global__ void ctc_pass1_gen(const float* __restrict__ feat,
                              float* __restrict__ tok_out,
                              int rows, int V) {
    int warp = (blockIdx.x * blockDim.x + threadIdx.x) >> 5;
    int lane = threadIdx.x & 31;
    if (warp >= rows) return;
    const float* row = feat + (size_t)warp * V;

    float m = -INFINITY; int mi = 0;
    for (int i = lane; i < V; i += 32) {
        float x = row[i];
        if (x > m) { m = x; mi = i; }
    }
    #pragma unroll
    for (int o = 16; o; o >>= 1) {
        float om = __shfl_xor_sync(0xFFFFFFFFu, m, o);
        int   oi = __shfl_xor_sync(0xFFFFFFFFu, mi, o);
        if (om > m || (om == m && oi < mi)) { m = om; mi = oi; }
    }
    float s = 0.f;
    for (int i = lane; i < V; i += 32) s += __expf(row[i] - m);
    #pragma unroll
    for (int o = 16; o; o >>= 1) s += __shfl_xor_sync(0xFFFFFFFFu, s, o);
    if (lane == 0) { tok_out[warp] = (float)mi; g_maxscore[warp] = -__logf(s); }
}

// ---------------------------------------------------------------------------
// Pass 2 (vectorized, T%4==0): one block per batch; float4 keep + masked
// score reduction. keep = (tok!=0) && (tok!=prev) && (t<len)
// ---------------------------------------------------------------------------
__global__ void ctc_pass2_vec(const float* __restrict__ tok,
                              const int* __restrict__ lengths,
                              float* __restrict__ keep_out,
                              float* __restrict__ score_out,
                              int T) {
    const int b   = blockIdx.x;
    const int len = lengths[b];
    const size_t base = (size_t)b * T;
    const float4* t4 = reinterpret_cast<const float4*>(tok + base);
    const float4* s4 = reinterpret_cast<const float4*>(g_maxscore + base);
    float4* k4       = reinterpret_cast<float4*>(keep_out + base);
    const int n4 = T >> 2;

    float acc = 0.f;
    for (int i = threadIdx.x; i < n4; i += blockDim.x) {
        float4 tv = t4[i];
        int p  = (i == 0) ? 0 : (int)tok[base + 4 * i - 1];
        int t0 = (int)tv.x, t1 = (int)tv.y, t2 = (int)tv.z, t3 = (int)tv.w;
        int tb = 4 * i;
        float4 kv;
        kv.x = (t0 != 0 && t0 != p  && tb     < len) ? 1.f : 0.f;
        kv.y = (t1 != 0 && t1 != t0 && tb + 1 < len) ? 1.f : 0.f;
        kv.z = (t2 != 0 && t2 != t1 && tb + 2 < len) ? 1.f : 0.f;
        kv.w = (t3 != 0 && t3 != t2 && tb + 3 < len) ? 1.f : 0.f;
        k4[i] = kv;

        float4 sv = s4[i];
        acc += (tb     < len ? sv.x : 0.f) + (tb + 1 < len ? sv.y : 0.f)
             + (tb + 2 < len ? sv.z : 0.f) + (tb + 3 < len ? sv.w : 0.f);
    }

    // warp reduce then cross-warp via smem
    #pragma unroll
    for (int o = 16; o; o >>= 1) acc += __shfl_xor_sync(0xFFFFFFFFu, acc, o);
    __shared__ float sh[32];
    int wid = threadIdx.x >> 5;
    if ((threadIdx.x & 31) == 0) sh[wid] = acc;
    __syncthreads();
    if (threadIdx.x == 0) {
        float s = 0.f;
        int nw = blockDim.x >> 5;
        for (int w = 0; w < nw; w++) s += sh[w];
        score_out[b] = s;
    }
}

// Scalar fallback pass2 (any T)
__global__ void ctc_pass2_gen(const float* __restrict__ tok,
                              const int* __restrict__ lengths,
                              float* __restrict__ keep_out,
                              float* __restrict__ score_out,
                              int T) {
    int b = blockIdx.x;
    int len = lengths[b];
    const float* trow = tok + (size_t)b * T;
    float* krow = keep_out + (size_t)b * T;
    const float* srow = g_maxscore + (size_t)b * T;

    float acc = 0.f;
    for (int t = threadIdx.x; t < T; t += blockDim.x) {
        int cur  = (int)trow[t];
        int prev = (t == 0) ? 0 : (int)trow[t - 1];
        bool valid = (t < len);
        krow[t] = (cur != 0 && cur != prev && valid) ? 1.f : 0.f;
        if (valid) acc += srow[t];
    }
    #pragma unroll
    for (int o = 16; o; o >>= 1) acc += __shfl_xor_sync(0xFFFFFFFFu, acc, o);
    __shared__ float sh[32];
    int wid = threadIdx.x >> 5;
    if ((threadIdx.x & 31) == 0) sh[wid] = acc;
    __syncthreads();
    if (threadIdx.x == 0) {
        float s = 0.f;
        int nw = blockDim.x >> 5;
        for (int w = 0; w < nw; w++) s += sh[w];
        score_out[b] = s;
    }
}

extern "C" void kernel_launch(void* const* d_in, const int* in_sizes, int n_in,
                              void* d_out, int out_size) {
    const float* feat    = (const float*)d_in[0];
    const int*   lengths = (const int*)d_in[1];

    int B = in_sizes[1];
    int T = (out_size - B) / (2 * B);          // out = tokens(B*T) + keep(B*T) + scores(B)
    int V = (int)((long long)in_sizes[0] / ((long long)B * T));
    int rows = B * T;

    float* out   = (float*)d_out;
    float* tok   = out;
    float* keep  = out + (size_t)rows;
    float* score = out + 2 * (size_t)rows;

    if (V == 128 && (rows & 3) == 0) {
        const int threads = 256;               // 8 warps/block
        int blocks = 148 * 8;                  // grid-stride, ~7 iters/warp
        int maxBlocks = (rows / 4 + 7) / 8;
        if (blocks > maxBlocks) blocks = maxBlocks;
        ctc_pass1_v128x4<<<blocks, threads>>>(feat, tok, rows);
    } else {
        int blocks = (rows + 7) / 8;
        ctc_pass1_gen<<<blocks, 256>>>(feat, tok, rows, V);
    }

    if ((T & 3) == 0) {
        ctc_pass2_vec<<<B, 512>>>(tok, lengths, keep, score, T);
    } else {
        ctc_pass2_gen<<<B, 256>>>(tok, lengths, keep, score, T);
    }
}